// round 4
// baseline (speedup 1.0000x reference)
#include <cuda_runtime.h>
#include <cuda_bf16.h>
#include <cstdint>

// ---------------------------------------------------------------------------
// RPN: 1x1 conv GEMM -> softmax/decode/clip -> top-12000 select+sort -> greedy NMS
// Outputs: rpn_locs[8,36864,4] | rpn_scores[8,36864,2] | rois[8,600,4] | anchor[1,36864,4]
// Score GEMM accumulation = splitK2 (two contiguous 256-k ascending chains, p0+p1)
// to bit-match the reference; loc GEMM = single ascending chain (proven exact).
// ---------------------------------------------------------------------------

#define NB        8
#define NA        36864
#define HW        4096
#define K_DIM     512
#define N_PRE     12000
#define N_POST    600
#define SORT_N    16384

#define OFF_SCORES 1179648
#define OFF_ROIS   1769472
#define OFF_ANCH   1788672

__device__ float4             g_boxes[NB][NA];
__device__ unsigned           g_su[NB][NA];
__device__ unsigned long long g_cand[NB][SORT_N];
__device__ int                g_C[NB];
__device__ int                g_vcnt[NB];
__device__ float4             g_sboxes[NB][N_PRE];

__constant__ float c_aw[9] = {181.01933598375618f, 362.03867196751236f, 724.0773439350247f,
                              128.0f, 256.0f, 512.0f,
                              90.50966799187809f, 181.01933598375618f, 362.03867196751236f};
__constant__ float c_ah[9] = {90.50966799187809f, 181.01933598375618f, 362.03867196751236f,
                              128.0f, 256.0f, 512.0f,
                              181.01933598375618f, 362.03867196751236f, 724.0773439350247f};

// ---------------------------------------------------------------------------
// K1: fused GEMM. 256 blocks (8 n * 32 hw-tiles of 128), 128 threads.
// Locs (36 ch): single ascending-k chain.
// Scores (18 ch): two 256-k contiguous chains folded p0+p1 (cuBLAS splitK2).
// ---------------------------------------------------------------------------
__global__ __launch_bounds__(128) void gemm_kernel(
    const float* __restrict__ x,
    const float* __restrict__ wsc, const float* __restrict__ bsc,
    const float* __restrict__ wlc, const float* __restrict__ blc,
    float* __restrict__ out)
{
    __shared__ float xs[64 * 128];      // [k][hw]
    __shared__ float ws[54 * 64];       // [o][k]
    const int t   = threadIdx.x;
    const int b   = blockIdx.x;
    const int n   = b >> 5;
    const int hw0 = (b & 31) * 128;
    const float* xb = x + n * (K_DIM * HW) + hw0;

    float acc[36];
    float p0[18], p1[18];
#pragma unroll
    for (int o = 0; o < 36; o++) acc[o] = 0.0f;
#pragma unroll
    for (int o = 0; o < 18; o++) { p0[o] = 0.0f; p1[o] = 0.0f; }

    for (int k0 = 0; k0 < K_DIM; k0 += 64) {
#pragma unroll
        for (int it = 0; it < 16; it++) {
            int v = t + it * 128;
            int r = v >> 5;
            int c = v & 31;
            float4 val = *(const float4*)(xb + (k0 + r) * HW + c * 4);
            *(float4*)&xs[r * 128 + c * 4] = val;
        }
        for (int v = t; v < 864; v += 128) {
            int o = v >> 4;
            int c = v & 15;
            const float* row = (o < 36) ? (wlc + o * K_DIM) : (wsc + (o - 36) * K_DIM);
            *(float4*)&ws[o * 64 + c * 4] = *(const float4*)(row + k0 + c * 4);
        }
        __syncthreads();

        float* sc = (k0 < 256) ? p0 : p1;   // splitK2 slice for scores
        for (int kk = 0; kk < 64; kk += 4) {
            float x0 = xs[(kk + 0) * 128 + t];
            float x1 = xs[(kk + 1) * 128 + t];
            float x2 = xs[(kk + 2) * 128 + t];
            float x3 = xs[(kk + 3) * 128 + t];
#pragma unroll
            for (int o = 0; o < 36; o++) {
                float4 w4 = *(float4*)&ws[o * 64 + kk];
                acc[o] = fmaf(x0, w4.x, acc[o]);
                acc[o] = fmaf(x1, w4.y, acc[o]);
                acc[o] = fmaf(x2, w4.z, acc[o]);
                acc[o] = fmaf(x3, w4.w, acc[o]);
            }
#pragma unroll
            for (int o = 0; o < 18; o++) {
                float4 w4 = *(float4*)&ws[(36 + o) * 64 + kk];
                sc[o] = fmaf(x0, w4.x, sc[o]);
                sc[o] = fmaf(x1, w4.y, sc[o]);
                sc[o] = fmaf(x2, w4.z, sc[o]);
                sc[o] = fmaf(x3, w4.w, sc[o]);
            }
        }
        __syncthreads();
    }

    const int hw = hw0 + t;
    float* lout = out + n * (NA * 4) + hw * 36;
#pragma unroll
    for (int o = 0; o < 36; o++) lout[o] = acc[o] + blc[o];
    float* sout = out + OFF_SCORES + n * (NA * 2) + hw * 18;
#pragma unroll
    for (int o = 0; o < 18; o++) sout[o] = (p0[o] + p1[o]) + bsc[o];
}

// ---------------------------------------------------------------------------
// K2: decode boxes + fg score + validity + anchors
// ---------------------------------------------------------------------------
__global__ void decode_kernel(float* __restrict__ out)
{
    int g = blockIdx.x * blockDim.x + threadIdx.x;
    if (g >= NB * NA) return;
    int n = g / NA;
    int i = g - n * NA;
    int hw = i / 9;
    int a  = i - hw * 9;

    float sx = (float)((hw & 63) * 16);
    float sy = (float)((hw >> 6) * 16);
    float aw = c_aw[a], ah = c_ah[a];
    float ax1 = sx - 0.5f * aw, ay1 = sy - 0.5f * ah;
    float ax2 = sx + 0.5f * aw, ay2 = sy + 0.5f * ah;

    if (n == 0) {
        *(float4*)(out + OFF_ANCH + i * 4) = make_float4(ax1, ay1, ax2, ay2);
    }

    float aww = ax2 - ax1, ahh = ay2 - ay1;
    float acx = ax1 + 0.5f * aww, acy = ay1 + 0.5f * ahh;

    float4 l = *(const float4*)(out + n * (NA * 4) + i * 4);
    float cx = l.x * aww + acx;
    float cy = l.y * ahh + acy;
    float w  = expf(l.z) * aww;
    float h  = expf(l.w) * ahh;

    float x1 = fminf(fmaxf(cx - 0.5f * w, 0.0f), 1024.0f);
    float y1 = fminf(fmaxf(cy - 0.5f * h, 0.0f), 1024.0f);
    float x2 = fminf(fmaxf(cx + 0.5f * w, 0.0f), 1024.0f);
    float y2 = fminf(fmaxf(cy + 0.5f * h, 0.0f), 1024.0f);

    bool valid = ((x2 - x1) >= 16.0f) && ((y2 - y1) >= 16.0f);

    float2 s = *(const float2*)(out + OFF_SCORES + n * (NA * 2) + i * 2);
    float m  = fmaxf(s.x, s.y);
    float e0 = expf(s.x - m), e1 = expf(s.y - m);
    float fg = e1 / (e0 + e1);

    g_su[n][i]    = valid ? (__float_as_uint(fg) | 0x80000000u) : 0u;
    g_boxes[n][i] = make_float4(x1, y1, x2, y2);
}

// ---------------------------------------------------------------------------
// K3: per-batch 2-level 12-bit radix select to ~N_PRE candidates
// ---------------------------------------------------------------------------
__global__ __launch_bounds__(1024) void select_kernel()
{
    __shared__ unsigned hist[4096];
    __shared__ unsigned psum[256];
    __shared__ int sB1, sAbove, sThr, sCnt;

    const int n = blockIdx.x;
    const int t = threadIdx.x;

    for (int v = t; v < 4096; v += 1024) hist[v] = 0;
    __syncthreads();
    for (int i = t; i < NA; i += 1024) {
        unsigned u = g_su[n][i];
        if (u) atomicAdd(&hist[u >> 20], 1u);
    }
    __syncthreads();
    if (t < 256) {
        unsigned s = 0;
#pragma unroll
        for (int j = 0; j < 16; j++) s += hist[t * 16 + j];
        psum[t] = s;
    }
    __syncthreads();
    if (t == 0) {
        unsigned total = 0;
        for (int c = 0; c < 256; c++) total += psum[c];
        if (total <= N_PRE) {
            sThr = 1;
            sB1  = -1;
            g_vcnt[n] = (int)total;
        } else {
            g_vcnt[n] = N_PRE;
            unsigned acc = 0; int c = 255;
            while (acc + psum[c] < N_PRE) { acc += psum[c]; c--; }
            int bkt = c * 16 + 15;
            while (acc + hist[bkt] < N_PRE) { acc += hist[bkt]; bkt--; }
            sB1 = bkt; sAbove = (int)acc; sThr = 0;
        }
    }
    __syncthreads();
    const int B1 = sB1;
    if (sThr == 0) {
        for (int v = t; v < 4096; v += 1024) hist[v] = 0;
        __syncthreads();
        for (int i = t; i < NA; i += 1024) {
            unsigned u = g_su[n][i];
            if (u && (int)(u >> 20) == B1) atomicAdd(&hist[(u >> 8) & 0xFFFu], 1u);
        }
        __syncthreads();
        if (t < 256) {
            unsigned s = 0;
#pragma unroll
            for (int j = 0; j < 16; j++) s += hist[t * 16 + j];
            psum[t] = s;
        }
        __syncthreads();
        if (t == 0) {
            unsigned K2 = (unsigned)(N_PRE - sAbove);
            unsigned acc = 0; int c = 255;
            while (acc + psum[c] < K2) { acc += psum[c]; c--; }
            int bkt = c * 16 + 15;
            while (acc + hist[bkt] < K2) { acc += hist[bkt]; bkt--; }
            sThr = (B1 << 12) | bkt;
        }
    }
    __syncthreads();
    const unsigned thr = (unsigned)sThr;
    if (t == 0) sCnt = 0;
    __syncthreads();
    for (int i = t; i < NA; i += 1024) {
        unsigned u = g_su[n][i];
        if (u && (u >> 8) >= thr) {
            int p = atomicAdd(&sCnt, 1);
            if (p < SORT_N)
                g_cand[n][p] = (((unsigned long long)u) << 32) | (unsigned)(~i);
        }
    }
    __syncthreads();
    if (t == 0) g_C[n] = min(sCnt, SORT_N);
}

// ---------------------------------------------------------------------------
// K4: per-batch smem bitonic sort (descending) of 16384 64-bit keys
// ---------------------------------------------------------------------------
__global__ __launch_bounds__(1024) void sort_kernel()
{
    extern __shared__ unsigned long long keys[];
    const int n = blockIdx.x;
    const int t = threadIdx.x;
    const int C = g_C[n];

    for (int i = t; i < SORT_N; i += 1024)
        keys[i] = (i < C) ? g_cand[n][i] : 0ull;
    __syncthreads();

    for (int k = 2; k <= SORT_N; k <<= 1) {
        for (int j = k >> 1; j > 0; j >>= 1) {
            for (int i = t; i < SORT_N; i += 1024) {
                int l = i ^ j;
                if (l > i) {
                    unsigned long long a = keys[i], b = keys[l];
                    bool up = ((i & k) == 0);
                    if ((a < b) == up) { keys[i] = b; keys[l] = a; }
                }
            }
            __syncthreads();
        }
    }

    for (int p = t; p < N_PRE; p += 1024) {
        unsigned long long kk = keys[p];
        unsigned idx = ~(unsigned)(kk & 0xFFFFFFFFull);
        float4 b = (kk != 0ull) ? g_boxes[n][idx] : make_float4(0.f, 0.f, 0.f, 0.f);
        g_sboxes[n][p] = b;
    }
}

// ---------------------------------------------------------------------------
// K5: greedy NMS. 1 block/batch, 12 register-resident boxes/thread + live mask.
// ---------------------------------------------------------------------------
__global__ __launch_bounds__(1024) void nms_kernel(float* __restrict__ out)
{
    __shared__ int warpmin[32];
    __shared__ int s_next;
    __shared__ int s_keep[N_POST];

    const int n = blockIdx.x;
    const int t = threadIdx.x;
    const int vcnt = g_vcnt[n];
    const int base = t * 12;

    float bx1[12], by1[12], bx2[12], by2[12], ar[12];
    unsigned live = 0;
#pragma unroll
    for (int s = 0; s < 12; s++) {
        int i = base + s;
        if (i < vcnt) {
            float4 b = g_sboxes[n][i];
            bx1[s] = b.x; by1[s] = b.y; bx2[s] = b.z; by2[s] = b.w;
            ar[s] = fmaxf(b.z - b.x, 0.f) * fmaxf(b.w - b.y, 0.f);
            live |= 1u << s;
        } else {
            bx1[s] = 0.f; by1[s] = 0.f; bx2[s] = 0.f; by2[s] = 0.f; ar[s] = 0.f;
        }
    }

    int kept = 0;
    while (kept < N_POST) {
        int lm = live ? (base + __ffs(live) - 1) : 0x7FFFFFFF;
        lm = __reduce_min_sync(0xFFFFFFFFu, lm);
        if ((t & 31) == 0) warpmin[t >> 5] = lm;
        __syncthreads();
        if (t < 32) {
            int v = warpmin[t];
            v = __reduce_min_sync(0xFFFFFFFFu, v);
            if (t == 0) {
                s_next = v;
                if (v != 0x7FFFFFFF) s_keep[kept] = v;
            }
        }
        __syncthreads();
        int nxt = s_next;
        if (nxt == 0x7FFFFFFF) break;
        kept++;

        float4 cb = g_sboxes[n][nxt];
        float ca = fmaxf(cb.z - cb.x, 0.f) * fmaxf(cb.w - cb.y, 0.f);
        int rel = nxt - base;
        if (rel >= 0 && rel < 12) live &= ~(1u << rel);

        if (live) {
            float lo = 0.69f * ca;
#pragma unroll
            for (int s = 0; s < 12; s++) {
                if (live & (1u << s)) {
                    float a1 = ar[s];
                    if (a1 < lo || ca < 0.69f * a1) continue;      // conservative prune
                    float iw = fminf(bx2[s], cb.z) - fmaxf(bx1[s], cb.x);
                    if (iw <= 0.f) continue;
                    float ih = fminf(by2[s], cb.w) - fmaxf(by1[s], cb.y);
                    if (ih <= 0.f) continue;
                    float inter = iw * ih;
                    float iou = inter / (ca + a1 - inter + 1e-9f);
                    if (iou > 0.7f)
                        live &= ~(1u << s);
                }
            }
        }
    }

    __syncthreads();
    for (int e = t; e < N_POST; e += 1024) {
        int ki = (e < kept) ? s_keep[e] : (e - kept);
        float4 b = g_sboxes[n][ki];
        *(float4*)(out + OFF_ROIS + n * (N_POST * 4) + e * 4) = b;
    }
}

// ---------------------------------------------------------------------------
extern "C" void kernel_launch(void* const* d_in, const int* in_sizes, int n_in,
                              void* d_out, int out_size)
{
    const float* x   = (const float*)d_in[0];
    const float* wsc = (const float*)d_in[1];
    const float* bsc = (const float*)d_in[2];
    const float* wlc = (const float*)d_in[3];
    const float* blc = (const float*)d_in[4];
    float* out = (float*)d_out;

    cudaFuncSetAttribute(sort_kernel, cudaFuncAttributeMaxDynamicSharedMemorySize,
                         SORT_N * (int)sizeof(unsigned long long));

    gemm_kernel<<<256, 128>>>(x, wsc, bsc, wlc, blc, out);
    decode_kernel<<<(NB * NA + 255) / 256, 256>>>(out);
    select_kernel<<<NB, 1024>>>();
    sort_kernel<<<NB, 1024, SORT_N * sizeof(unsigned long long)>>>();
    nms_kernel<<<NB, 1024>>>(out);
}